// round 2
// baseline (speedup 1.0000x reference)
#include <cuda_runtime.h>
#include <math.h>

#define NMAT 256
#define DD 64
#define NSWEEP 10

__device__ float g_L[NMAT * DD * DD];      // log(X_i)
__device__ float g_S[NMAT * DD * DD];      // log(X_i) + M_i
__device__ float g_gramp[4 * NMAT * NMAT];
__device__ float g_W[NMAT * NMAT];
__device__ float g_sq[NMAT];
__device__ float g_ss[NMAT];
__device__ float g_row[NMAT];
__device__ float g_col[NMAT];

__device__ __forceinline__ float blk_reduce(float v, float* red, int tid) {
#pragma unroll
    for (int o = 16; o >= 1; o >>= 1) v += __shfl_xor_sync(0xffffffffu, v, o);
    if ((tid & 31) == 0) red[tid >> 5] = v;
    __syncthreads();
    if (tid == 0) {
        float s = 0.f;
#pragma unroll
        for (int w = 0; w < 8; w++) s += red[w];
        red[0] = s;
    }
    __syncthreads();
    float r = red[0];
    __syncthreads();
    return r;
}

// ============================================================
// Kernel 1: one-sided Jacobi -> log(X); also sq=||L||_F^2, ss=sum(L)
// ============================================================
__global__ void __launch_bounds__(256) jacobi_log_kernel(const float* __restrict__ X) {
    __shared__ float G[64 * 68];   // column-major, stride 68
    __shared__ float coef[64];
    __shared__ float red[8];
    const int tid = threadIdx.x;
    const int mat = blockIdx.x;
    const float* Xm = X + (size_t)mat * 4096;

#pragma unroll
    for (int l = 0; l < 16; l++) {
        int idx = tid + l * 256;
        G[(idx >> 6) * 68 + (idx & 63)] = Xm[idx];   // X symmetric
    }
    __syncthreads();

    const int pr = tid >> 3;   // pair 0..31
    const int sub = tid & 7;   // 8 rows x (2 float4) per thread

    for (int sweep = 0; sweep < NSWEEP; sweep++) {
        for (int r = 0; r < 63; r++) {
            int a, b;
            if (pr == 0) { a = 63; b = r; }
            else {
                int x = r + pr;       if (x >= 63) x -= 63;
                int y = r + 63 - pr;  if (y >= 63) y -= 63;
                a = x; b = y;
            }
            int p = a < b ? a : b;
            int q = a < b ? b : a;

            float* gp = &G[p * 68 + sub * 8];
            float* gq = &G[q * 68 + sub * 8];
            float4 P0 = *(const float4*)gp;
            float4 P1 = *(const float4*)(gp + 4);
            float4 Q0 = *(const float4*)gq;
            float4 Q1 = *(const float4*)(gq + 4);

            float dpp = P0.x*P0.x + P0.y*P0.y + P0.z*P0.z + P0.w*P0.w
                      + P1.x*P1.x + P1.y*P1.y + P1.z*P1.z + P1.w*P1.w;
            float dqq = Q0.x*Q0.x + Q0.y*Q0.y + Q0.z*Q0.z + Q0.w*Q0.w
                      + Q1.x*Q1.x + Q1.y*Q1.y + Q1.z*Q1.z + Q1.w*Q1.w;
            float dpq = P0.x*Q0.x + P0.y*Q0.y + P0.z*Q0.z + P0.w*Q0.w
                      + P1.x*Q1.x + P1.y*Q1.y + P1.z*Q1.z + P1.w*Q1.w;
#pragma unroll
            for (int o = 1; o < 8; o <<= 1) {
                dpp += __shfl_xor_sync(0xffffffffu, dpp, o);
                dqq += __shfl_xor_sync(0xffffffffu, dqq, o);
                dpq += __shfl_xor_sync(0xffffffffu, dpq, o);
            }

            if (dpq != 0.f) {
                float tau = (dqq - dpp) / (2.f * dpq);
                float t = 1.f / (fabsf(tau) + sqrtf(1.f + tau * tau));
                t = (tau >= 0.f) ? t : -t;
                float c = rsqrtf(1.f + t * t);
                float s = t * c;
                float4 R0, R1, U0, U1;
                R0.x = c*P0.x - s*Q0.x;  U0.x = s*P0.x + c*Q0.x;
                R0.y = c*P0.y - s*Q0.y;  U0.y = s*P0.y + c*Q0.y;
                R0.z = c*P0.z - s*Q0.z;  U0.z = s*P0.z + c*Q0.z;
                R0.w = c*P0.w - s*Q0.w;  U0.w = s*P0.w + c*Q0.w;
                R1.x = c*P1.x - s*Q1.x;  U1.x = s*P1.x + c*Q1.x;
                R1.y = c*P1.y - s*Q1.y;  U1.y = s*P1.y + c*Q1.y;
                R1.z = c*P1.z - s*Q1.z;  U1.z = s*P1.z + c*Q1.z;
                R1.w = c*P1.w - s*Q1.w;  U1.w = s*P1.w + c*Q1.w;
                *(float4*)gp = R0;  *(float4*)(gp + 4) = R1;
                *(float4*)gq = U0;  *(float4*)(gq + 4) = U1;
            }
            __syncthreads();
        }
    }

    // lambda_j = ||g_j||; log X = sum_j (log l / l^2) g_j g_j^T
    if (tid < 64) {
        float n2 = 0.f;
#pragma unroll 8
        for (int k = 0; k < 64; k++) { float g = G[tid * 68 + k]; n2 += g * g; }
        coef[tid] = 0.5f * logf(n2) / n2;
    }
    __syncthreads();

    const int ty = tid >> 4, tx = tid & 15;
    const int r0 = ty * 4, c0 = tx * 4;
    float acc[4][4];
#pragma unroll
    for (int i = 0; i < 4; i++)
#pragma unroll
        for (int j = 0; j < 4; j++) acc[i][j] = 0.f;

#pragma unroll 4
    for (int j = 0; j < 64; j++) {
        float cf = coef[j];
        float a0 = G[j * 68 + r0 + 0] * cf;
        float a1 = G[j * 68 + r0 + 1] * cf;
        float a2 = G[j * 68 + r0 + 2] * cf;
        float a3 = G[j * 68 + r0 + 3] * cf;
        float b0 = G[j * 68 + c0 + 0];
        float b1 = G[j * 68 + c0 + 1];
        float b2 = G[j * 68 + c0 + 2];
        float b3 = G[j * 68 + c0 + 3];
        acc[0][0] += a0*b0; acc[0][1] += a0*b1; acc[0][2] += a0*b2; acc[0][3] += a0*b3;
        acc[1][0] += a1*b0; acc[1][1] += a1*b1; acc[1][2] += a1*b2; acc[1][3] += a1*b3;
        acc[2][0] += a2*b0; acc[2][1] += a2*b1; acc[2][2] += a2*b2; acc[2][3] += a2*b3;
        acc[3][0] += a3*b0; acc[3][1] += a3*b1; acc[3][2] += a3*b2; acc[3][3] += a3*b3;
    }

    float s1 = 0.f, s2 = 0.f;
    float* Lm = g_L + (size_t)mat * 4096;
#pragma unroll
    for (int i = 0; i < 4; i++)
#pragma unroll
        for (int j = 0; j < 4; j++) {
            float v = acc[i][j];
            Lm[(r0 + i) * 64 + c0 + j] = v;
            s1 += v;
            s2 += v * v;
        }
    float ts1 = blk_reduce(s1, red, tid);
    float ts2 = blk_reduce(s2, red, tid);
    if (tid == 0) { g_ss[mat] = ts1; g_sq[mat] = ts2; }
}

// ============================================================
// Kernel 2: split-K Gram: gramp[z][i][j] = sum_{m in z-chunk} L_i[m] L_j[m]
// ============================================================
__global__ void __launch_bounds__(256) gram_kernel() {
    __shared__ float At[32 * 65];
    __shared__ float Bt[32 * 65];
    const int tid = threadIdx.x;
    const int i0 = blockIdx.x * 32, j0 = blockIdx.y * 32, z = blockIdx.z;
    const int kb = z * 1024;
    const int ty = tid >> 4, tx = tid & 15;
    float a00 = 0.f, a01 = 0.f, a10 = 0.f, a11 = 0.f;

    for (int kt = 0; kt < 16; kt++) {
        int kbase = kb + kt * 64;
#pragma unroll
        for (int l = 0; l < 8; l++) {
            int idx = tid + l * 256;
            int rr = idx >> 6, cc = idx & 63;
            At[rr * 65 + cc] = g_L[(size_t)(i0 + rr) * 4096 + kbase + cc];
            Bt[rr * 65 + cc] = g_L[(size_t)(j0 + rr) * 4096 + kbase + cc];
        }
        __syncthreads();
#pragma unroll 8
        for (int kk = 0; kk < 64; kk++) {
            float x0 = At[(2 * ty) * 65 + kk], x1 = At[(2 * ty + 1) * 65 + kk];
            float y0 = Bt[(2 * tx) * 65 + kk], y1 = Bt[(2 * tx + 1) * 65 + kk];
            a00 += x0 * y0; a01 += x0 * y1; a10 += x1 * y0; a11 += x1 * y1;
        }
        __syncthreads();
    }
    float* gp = g_gramp + (size_t)z * NMAT * NMAT;
    gp[(i0 + 2*ty)     * NMAT + j0 + 2*tx]     = a00;
    gp[(i0 + 2*ty)     * NMAT + j0 + 2*tx + 1] = a01;
    gp[(i0 + 2*ty + 1) * NMAT + j0 + 2*tx]     = a10;
    gp[(i0 + 2*ty + 1) * NMAT + j0 + 2*tx + 1] = a11;
}

// ============================================================
// Kernel 3: W + row sums
// ============================================================
__global__ void __launch_bounds__(256) w_kernel(const float* __restrict__ bwp) {
    __shared__ float red[8];
    const int i = blockIdx.x, j = threadIdx.x;
    const float bw = bwp[0];
    const float inv = 0.5f / (bw * bw);
    float gram = g_gramp[i * NMAT + j]
               + g_gramp[1 * NMAT * NMAT + i * NMAT + j]
               + g_gramp[2 * NMAT * NMAT + i * NMAT + j]
               + g_gramp[3 * NMAT * NMAT + i * NMAT + j];
    float pds = g_sq[i] + g_sq[j] - 2.f * gram
              + 2.0e-7f * (g_ss[j] - g_ss[i]) + 4.096e-11f;
    float w = expf(-pds * inv);
    g_W[i * NMAT + j] = w;
    float rs = blk_reduce(w, red, j);
    if (j == 0) g_row[i] = rs;
}

// Kernel 4: column sums
__global__ void __launch_bounds__(256) col_kernel() {
    __shared__ float red[8];
    const int k = blockIdx.x, j = threadIdx.x;
    float w = g_W[j * NMAT + k];
    float cs = blk_reduce(w, red, j);
    if (j == 0) g_col[k] = cs;
}

// ============================================================
// Kernel 5: C[k] = sum_j W[j,k] L_j ; S = L + (C - col*L)/row
// grid (8 k-tiles, 32 e-tiles), tile 32k x 128e
// ============================================================
__global__ void __launch_bounds__(256) m_kernel() {
    __shared__ float Ws[32 * 33];
    __shared__ float Ls[32 * 128];
    const int tid = threadIdx.x;
    const int k0 = blockIdx.x * 32;
    const int e0 = blockIdx.y * 128;
    const int kk = tid >> 3;
    const int ee = (tid & 7) * 16;
    float4 acc[4];
#pragma unroll
    for (int i = 0; i < 4; i++) acc[i] = make_float4(0.f, 0.f, 0.f, 0.f);

    for (int jt = 0; jt < 8; jt++) {
        int j0 = jt * 32;
#pragma unroll
        for (int l = 0; l < 4; l++) {
            int idx = tid + l * 256;
            int j = idx >> 5, k = idx & 31;
            Ws[j * 33 + k] = g_W[(size_t)(j0 + j) * NMAT + k0 + k];
        }
#pragma unroll
        for (int l = 0; l < 4; l++) {
            int idx = tid + l * 256;          // float4 index in [0,1024)
            int j = idx >> 5, c4 = idx & 31;
            ((float4*)Ls)[j * 32 + c4] =
                ((const float4*)(g_L + (size_t)(j0 + j) * 4096 + e0))[c4];
        }
        __syncthreads();
#pragma unroll 8
        for (int j = 0; j < 32; j++) {
            float w = Ws[j * 33 + kk];
            const float4* lr = (const float4*)(Ls + j * 128 + ee);
            float4 l0 = lr[0], l1 = lr[1], l2 = lr[2], l3 = lr[3];
            acc[0].x += w*l0.x; acc[0].y += w*l0.y; acc[0].z += w*l0.z; acc[0].w += w*l0.w;
            acc[1].x += w*l1.x; acc[1].y += w*l1.y; acc[1].z += w*l1.z; acc[1].w += w*l1.w;
            acc[2].x += w*l2.x; acc[2].y += w*l2.y; acc[2].z += w*l2.z; acc[2].w += w*l2.w;
            acc[3].x += w*l3.x; acc[3].y += w*l3.y; acc[3].z += w*l3.z; acc[3].w += w*l3.w;
        }
        __syncthreads();
    }

    const int k = k0 + kk;
    const float col = g_col[k];
    const float rinv = 1.f / g_row[k];
    const float4* Lk = (const float4*)(g_L + (size_t)k * 4096 + e0 + ee);
    float4* Sk = (float4*)(g_S + (size_t)k * 4096 + e0 + ee);
#pragma unroll
    for (int i = 0; i < 4; i++) {
        float4 lv = Lk[i];
        float4 o;
        o.x = lv.x + (acc[i].x - col * lv.x) * rinv;
        o.y = lv.y + (acc[i].y - col * lv.y) * rinv;
        o.z = lv.z + (acc[i].z - col * lv.z) * rinv;
        o.w = lv.w + (acc[i].w - col * lv.w) * rinv;
        Sk[i] = o;
    }
}

// ============================================================
// Kernel 6: exp(S) via scaling & squaring (S symmetric, deg-8 Taylor)
// ============================================================
__device__ __forceinline__ void mm64(const float* A, const float* B, float* C,
                                     float scale, int addI, int tid) {
    const int ty = tid >> 4, tx = tid & 15;
    const int r0 = ty * 4, c0 = tx * 4;
    float acc[4][4];
#pragma unroll
    for (int i = 0; i < 4; i++)
#pragma unroll
        for (int j = 0; j < 4; j++) acc[i][j] = 0.f;
#pragma unroll 4
    for (int k = 0; k < 64; k++) {
        float a0 = A[(r0 + 0) * 68 + k];
        float a1 = A[(r0 + 1) * 68 + k];
        float a2 = A[(r0 + 2) * 68 + k];
        float a3 = A[(r0 + 3) * 68 + k];
        float4 b = *(const float4*)&B[k * 68 + c0];
        acc[0][0] += a0*b.x; acc[0][1] += a0*b.y; acc[0][2] += a0*b.z; acc[0][3] += a0*b.w;
        acc[1][0] += a1*b.x; acc[1][1] += a1*b.y; acc[1][2] += a1*b.z; acc[1][3] += a1*b.w;
        acc[2][0] += a2*b.x; acc[2][1] += a2*b.y; acc[2][2] += a2*b.z; acc[2][3] += a2*b.w;
        acc[3][0] += a3*b.x; acc[3][1] += a3*b.y; acc[3][2] += a3*b.z; acc[3][3] += a3*b.w;
    }
#pragma unroll
    for (int i = 0; i < 4; i++)
#pragma unroll
        for (int j = 0; j < 4; j++) {
            float v = acc[i][j] * scale;
            if (addI && (r0 + i) == (c0 + j)) v += 1.f;
            C[(r0 + i) * 68 + c0 + j] = v;
        }
    __syncthreads();
}

__global__ void __launch_bounds__(256) expm_kernel(float* __restrict__ out) {
    __shared__ float T[64 * 68];
    __shared__ float Pa[64 * 68];
    __shared__ float Pb[64 * 68];
    __shared__ float red[8];
    const int tid = threadIdx.x;
    const int mat = blockIdx.x;
    const float* Sm = g_S + (size_t)mat * 4096;

    float fr = 0.f;
#pragma unroll
    for (int l = 0; l < 16; l++) {
        int idx = tid + l * 256;
        float v = Sm[idx];
        T[(idx >> 6) * 68 + (idx & 63)] = v;
        fr += v * v;
    }
    float fro2 = blk_reduce(fr, red, tid);
    float fro = sqrtf(fro2);

    int m = 0;
    float sc = 1.f;
    while (fro * sc > 0.25f && m < 30) { sc *= 0.5f; m++; }

    // scale T; init A = I + T/8 (deg-8 Horner innermost step)
#pragma unroll
    for (int l = 0; l < 16; l++) {
        int idx = tid + l * 256;
        int rr = idx >> 6, cc = idx & 63;
        float tv = T[rr * 68 + cc] * sc;
        T[rr * 68 + cc] = tv;
        Pa[rr * 68 + cc] = tv * 0.125f + (rr == cc ? 1.f : 0.f);
    }
    __syncthreads();

    float* pa = Pa;
    float* pb = Pb;
    // k = 7..1: A = I + (T*A)/k
#pragma unroll
    for (int k = 7; k >= 1; k--) {
        mm64(T, pa, pb, 1.f / (float)k, 1, tid);
        float* t = pa; pa = pb; pb = t;
    }
    // m squarings
    for (int sqr = 0; sqr < m; sqr++) {
        mm64(pa, pa, pb, 1.f, 0, tid);
        float* t = pa; pa = pb; pb = t;
    }

    float* om = out + (size_t)mat * 4096;
#pragma unroll
    for (int l = 0; l < 16; l++) {
        int idx = tid + l * 256;
        om[idx] = pa[(idx >> 6) * 68 + (idx & 63)];
    }
}

extern "C" void kernel_launch(void* const* d_in, const int* in_sizes, int n_in,
                              void* d_out, int out_size) {
    const float* X  = (const float*)d_in[0];
    const float* bw = (const float*)d_in[1];
    float* out = (float*)d_out;

    jacobi_log_kernel<<<NMAT, 256>>>(X);
    gram_kernel<<<dim3(8, 8, 4), 256>>>();
    w_kernel<<<NMAT, 256>>>(bw);
    col_kernel<<<NMAT, 256>>>();
    m_kernel<<<dim3(8, 32), 256>>>();
    expm_kernel<<<NMAT, 256>>>(out);
}

// round 3
// speedup vs baseline: 1.9007x; 1.9007x over previous
#include <cuda_runtime.h>
#include <math.h>

#define NMAT 256
#define DD 64
#define NSWEEP 8

__device__ float g_L[NMAT * DD * DD];      // log(X_i)
__device__ float g_S[NMAT * DD * DD];      // log(X_i) + M_i
__device__ float g_gramp[4 * NMAT * NMAT];
__device__ float g_W[NMAT * NMAT];
__device__ float g_sq[NMAT];
__device__ float g_ss[NMAT];
__device__ float g_row[NMAT];
__device__ float g_col[NMAT];

template <int NW>
__device__ __forceinline__ float blk_reduce(float v, float* red, int tid) {
#pragma unroll
    for (int o = 16; o >= 1; o >>= 1) v += __shfl_xor_sync(0xffffffffu, v, o);
    if ((tid & 31) == 0) red[tid >> 5] = v;
    __syncthreads();
    if (tid == 0) {
        float s = 0.f;
#pragma unroll
        for (int w = 0; w < NW; w++) s += red[w];
        red[0] = s;
    }
    __syncthreads();
    float r = red[0];
    __syncthreads();
    return r;
}

// ============================================================
// Kernel 1: one-sided Jacobi -> log(X); also sq=||L||_F^2, ss=sum(L)
// 128 threads: 4 threads per column-pair, 16 rows (4x float4) each.
// ============================================================
__global__ void __launch_bounds__(128) jacobi_log_kernel(const float* __restrict__ X) {
    __shared__ float G[64 * 68];   // column-major, stride 68 (272B = 17*16B)
    __shared__ float coef[64];
    __shared__ float red[4];
    const int tid = threadIdx.x;
    const int mat = blockIdx.x;
    const float* Xm = X + (size_t)mat * 4096;

#pragma unroll
    for (int l = 0; l < 32; l++) {
        int idx = tid + l * 128;
        G[(idx >> 6) * 68 + (idx & 63)] = Xm[idx];   // X symmetric
    }
    __syncthreads();

    const int pr = tid >> 2;   // pair 0..31
    const int sub = tid & 3;   // 16 rows (4 float4) per thread

    for (int sweep = 0; sweep < NSWEEP; sweep++) {
        for (int r = 0; r < 63; r++) {
            int a, b;
            if (pr == 0) { a = 63; b = r; }
            else {
                int x = r + pr;       if (x >= 63) x -= 63;
                int y = r + 63 - pr;  if (y >= 63) y -= 63;
                a = x; b = y;
            }
            int p = a < b ? a : b;
            int q = a < b ? b : a;

            float4* gp = (float4*)&G[p * 68 + sub * 16];
            float4* gq = (float4*)&G[q * 68 + sub * 16];
            float4 P[4], Q[4];
#pragma unroll
            for (int i = 0; i < 4; i++) { P[i] = gp[i]; Q[i] = gq[i]; }

            float dpp = 0.f, dqq = 0.f, dpq = 0.f;
#pragma unroll
            for (int i = 0; i < 4; i++) {
                dpp += P[i].x*P[i].x + P[i].y*P[i].y + P[i].z*P[i].z + P[i].w*P[i].w;
                dqq += Q[i].x*Q[i].x + Q[i].y*Q[i].y + Q[i].z*Q[i].z + Q[i].w*Q[i].w;
                dpq += P[i].x*Q[i].x + P[i].y*Q[i].y + P[i].z*Q[i].z + P[i].w*Q[i].w;
            }
#pragma unroll
            for (int o = 1; o < 4; o <<= 1) {
                dpp += __shfl_xor_sync(0xffffffffu, dpp, o);
                dqq += __shfl_xor_sync(0xffffffffu, dqq, o);
                dpq += __shfl_xor_sync(0xffffffffu, dpq, o);
            }

            if (dpq != 0.f) {
                float tau = (dqq - dpp) / (2.f * dpq);
                float t = 1.f / (fabsf(tau) + sqrtf(1.f + tau * tau));
                t = (tau >= 0.f) ? t : -t;
                float c = rsqrtf(1.f + t * t);
                float s = t * c;
#pragma unroll
                for (int i = 0; i < 4; i++) {
                    float4 R, U;
                    R.x = c*P[i].x - s*Q[i].x;  U.x = s*P[i].x + c*Q[i].x;
                    R.y = c*P[i].y - s*Q[i].y;  U.y = s*P[i].y + c*Q[i].y;
                    R.z = c*P[i].z - s*Q[i].z;  U.z = s*P[i].z + c*Q[i].z;
                    R.w = c*P[i].w - s*Q[i].w;  U.w = s*P[i].w + c*Q[i].w;
                    gp[i] = R;
                    gq[i] = U;
                }
            }
            __syncthreads();
        }
    }

    // lambda_j = ||g_j||; log X = sum_j (log l / l^2) g_j g_j^T
    if (tid < 64) {
        float n2 = 0.f;
#pragma unroll 8
        for (int k = 0; k < 64; k++) { float g = G[tid * 68 + k]; n2 += g * g; }
        coef[tid] = 0.5f * logf(n2) / n2;
    }
    __syncthreads();

    // outer-product accumulation: each thread computes an 8x4 block of L
    const int ty = tid >> 4, tx = tid & 15;        // ty 0..7, tx 0..15
    const int r0 = ty * 8, c0 = tx * 4;
    float acc[8][4];
#pragma unroll
    for (int i = 0; i < 8; i++)
#pragma unroll
        for (int j = 0; j < 4; j++) acc[i][j] = 0.f;

#pragma unroll 4
    for (int j = 0; j < 64; j++) {
        float cf = coef[j];
        float4 b = *(const float4*)&G[j * 68 + c0];
#pragma unroll
        for (int i = 0; i < 8; i++) {
            float av = G[j * 68 + r0 + i] * cf;
            acc[i][0] += av * b.x;
            acc[i][1] += av * b.y;
            acc[i][2] += av * b.z;
            acc[i][3] += av * b.w;
        }
    }

    float s1 = 0.f, s2 = 0.f;
    float* Lm = g_L + (size_t)mat * 4096;
#pragma unroll
    for (int i = 0; i < 8; i++) {
        float4 v;
        v.x = acc[i][0]; v.y = acc[i][1]; v.z = acc[i][2]; v.w = acc[i][3];
        *(float4*)&Lm[(r0 + i) * 64 + c0] = v;
        s1 += v.x + v.y + v.z + v.w;
        s2 += v.x*v.x + v.y*v.y + v.z*v.z + v.w*v.w;
    }
    float ts1 = blk_reduce<4>(s1, red, tid);
    float ts2 = blk_reduce<4>(s2, red, tid);
    if (tid == 0) { g_ss[mat] = ts1; g_sq[mat] = ts2; }
}

// ============================================================
// Kernel 2: split-K Gram: gramp[z][i][j] = sum_{m in z-chunk} L_i[m] L_j[m]
// ============================================================
__global__ void __launch_bounds__(256) gram_kernel() {
    __shared__ float At[32 * 65];
    __shared__ float Bt[32 * 65];
    const int tid = threadIdx.x;
    const int i0 = blockIdx.x * 32, j0 = blockIdx.y * 32, z = blockIdx.z;
    const int kb = z * 1024;
    const int ty = tid >> 4, tx = tid & 15;
    float a00 = 0.f, a01 = 0.f, a10 = 0.f, a11 = 0.f;

    for (int kt = 0; kt < 16; kt++) {
        int kbase = kb + kt * 64;
#pragma unroll
        for (int l = 0; l < 8; l++) {
            int idx = tid + l * 256;
            int rr = idx >> 6, cc = idx & 63;
            At[rr * 65 + cc] = g_L[(size_t)(i0 + rr) * 4096 + kbase + cc];
            Bt[rr * 65 + cc] = g_L[(size_t)(j0 + rr) * 4096 + kbase + cc];
        }
        __syncthreads();
#pragma unroll 8
        for (int kk = 0; kk < 64; kk++) {
            float x0 = At[(2 * ty) * 65 + kk], x1 = At[(2 * ty + 1) * 65 + kk];
            float y0 = Bt[(2 * tx) * 65 + kk], y1 = Bt[(2 * tx + 1) * 65 + kk];
            a00 += x0 * y0; a01 += x0 * y1; a10 += x1 * y0; a11 += x1 * y1;
        }
        __syncthreads();
    }
    float* gp = g_gramp + (size_t)z * NMAT * NMAT;
    gp[(i0 + 2*ty)     * NMAT + j0 + 2*tx]     = a00;
    gp[(i0 + 2*ty)     * NMAT + j0 + 2*tx + 1] = a01;
    gp[(i0 + 2*ty + 1) * NMAT + j0 + 2*tx]     = a10;
    gp[(i0 + 2*ty + 1) * NMAT + j0 + 2*tx + 1] = a11;
}

// ============================================================
// Kernel 3: W + row sums
// ============================================================
__global__ void __launch_bounds__(256) w_kernel(const float* __restrict__ bwp) {
    __shared__ float red[8];
    const int i = blockIdx.x, j = threadIdx.x;
    const float bw = bwp[0];
    const float inv = 0.5f / (bw * bw);
    float gram = g_gramp[i * NMAT + j]
               + g_gramp[1 * NMAT * NMAT + i * NMAT + j]
               + g_gramp[2 * NMAT * NMAT + i * NMAT + j]
               + g_gramp[3 * NMAT * NMAT + i * NMAT + j];
    float pds = g_sq[i] + g_sq[j] - 2.f * gram
              + 2.0e-7f * (g_ss[j] - g_ss[i]) + 4.096e-11f;
    float w = expf(-pds * inv);
    g_W[i * NMAT + j] = w;
    float rs = blk_reduce<8>(w, red, j);
    if (j == 0) g_row[i] = rs;
}

// Kernel 4: column sums
__global__ void __launch_bounds__(256) col_kernel() {
    __shared__ float red[8];
    const int k = blockIdx.x, j = threadIdx.x;
    float w = g_W[j * NMAT + k];
    float cs = blk_reduce<8>(w, red, j);
    if (j == 0) g_col[k] = cs;
}

// ============================================================
// Kernel 5: C[k] = sum_j W[j,k] L_j ; S = L + (C - col*L)/row
// ============================================================
__global__ void __launch_bounds__(256) m_kernel() {
    __shared__ float Ws[32 * 33];
    __shared__ float Ls[32 * 128];
    const int tid = threadIdx.x;
    const int k0 = blockIdx.x * 32;
    const int e0 = blockIdx.y * 128;
    const int kk = tid >> 3;
    const int ee = (tid & 7) * 16;
    float4 acc[4];
#pragma unroll
    for (int i = 0; i < 4; i++) acc[i] = make_float4(0.f, 0.f, 0.f, 0.f);

    for (int jt = 0; jt < 8; jt++) {
        int j0 = jt * 32;
#pragma unroll
        for (int l = 0; l < 4; l++) {
            int idx = tid + l * 256;
            int j = idx >> 5, k = idx & 31;
            Ws[j * 33 + k] = g_W[(size_t)(j0 + j) * NMAT + k0 + k];
        }
#pragma unroll
        for (int l = 0; l < 4; l++) {
            int idx = tid + l * 256;
            int j = idx >> 5, c4 = idx & 31;
            ((float4*)Ls)[j * 32 + c4] =
                ((const float4*)(g_L + (size_t)(j0 + j) * 4096 + e0))[c4];
        }
        __syncthreads();
#pragma unroll 8
        for (int j = 0; j < 32; j++) {
            float w = Ws[j * 33 + kk];
            const float4* lr = (const float4*)(Ls + j * 128 + ee);
            float4 l0 = lr[0], l1 = lr[1], l2 = lr[2], l3 = lr[3];
            acc[0].x += w*l0.x; acc[0].y += w*l0.y; acc[0].z += w*l0.z; acc[0].w += w*l0.w;
            acc[1].x += w*l1.x; acc[1].y += w*l1.y; acc[1].z += w*l1.z; acc[1].w += w*l1.w;
            acc[2].x += w*l2.x; acc[2].y += w*l2.y; acc[2].z += w*l2.z; acc[2].w += w*l2.w;
            acc[3].x += w*l3.x; acc[3].y += w*l3.y; acc[3].z += w*l3.z; acc[3].w += w*l3.w;
        }
        __syncthreads();
    }

    const int k = k0 + kk;
    const float col = g_col[k];
    const float rinv = 1.f / g_row[k];
    const float4* Lk = (const float4*)(g_L + (size_t)k * 4096 + e0 + ee);
    float4* Sk = (float4*)(g_S + (size_t)k * 4096 + e0 + ee);
#pragma unroll
    for (int i = 0; i < 4; i++) {
        float4 lv = Lk[i];
        float4 o;
        o.x = lv.x + (acc[i].x - col * lv.x) * rinv;
        o.y = lv.y + (acc[i].y - col * lv.y) * rinv;
        o.z = lv.z + (acc[i].z - col * lv.z) * rinv;
        o.w = lv.w + (acc[i].w - col * lv.w) * rinv;
        Sk[i] = o;
    }
}

// ============================================================
// Kernel 6: exp(S) via scaling & squaring (S symmetric, deg-8 Taylor)
// ============================================================
__device__ __forceinline__ void mm64(const float* A, const float* B, float* C,
                                     float scale, int addI, int tid) {
    const int ty = tid >> 4, tx = tid & 15;
    const int r0 = ty * 4, c0 = tx * 4;
    float acc[4][4];
#pragma unroll
    for (int i = 0; i < 4; i++)
#pragma unroll
        for (int j = 0; j < 4; j++) acc[i][j] = 0.f;
#pragma unroll 4
    for (int k = 0; k < 64; k++) {
        float a0 = A[(r0 + 0) * 68 + k];
        float a1 = A[(r0 + 1) * 68 + k];
        float a2 = A[(r0 + 2) * 68 + k];
        float a3 = A[(r0 + 3) * 68 + k];
        float4 b = *(const float4*)&B[k * 68 + c0];
        acc[0][0] += a0*b.x; acc[0][1] += a0*b.y; acc[0][2] += a0*b.z; acc[0][3] += a0*b.w;
        acc[1][0] += a1*b.x; acc[1][1] += a1*b.y; acc[1][2] += a1*b.z; acc[1][3] += a1*b.w;
        acc[2][0] += a2*b.x; acc[2][1] += a2*b.y; acc[2][2] += a2*b.z; acc[2][3] += a2*b.w;
        acc[3][0] += a3*b.x; acc[3][1] += a3*b.y; acc[3][2] += a3*b.z; acc[3][3] += a3*b.w;
    }
#pragma unroll
    for (int i = 0; i < 4; i++)
#pragma unroll
        for (int j = 0; j < 4; j++) {
            float v = acc[i][j] * scale;
            if (addI && (r0 + i) == (c0 + j)) v += 1.f;
            C[(r0 + i) * 68 + c0 + j] = v;
        }
    __syncthreads();
}

__global__ void __launch_bounds__(256) expm_kernel(float* __restrict__ out) {
    __shared__ float T[64 * 68];
    __shared__ float Pa[64 * 68];
    __shared__ float Pb[64 * 68];
    __shared__ float red[8];
    const int tid = threadIdx.x;
    const int mat = blockIdx.x;
    const float* Sm = g_S + (size_t)mat * 4096;

    float fr = 0.f;
#pragma unroll
    for (int l = 0; l < 16; l++) {
        int idx = tid + l * 256;
        float v = Sm[idx];
        T[(idx >> 6) * 68 + (idx & 63)] = v;
        fr += v * v;
    }
    float fro2 = blk_reduce<8>(fr, red, tid);
    float fro = sqrtf(fro2);

    int m = 0;
    float sc = 1.f;
    while (fro * sc > 0.25f && m < 30) { sc *= 0.5f; m++; }

#pragma unroll
    for (int l = 0; l < 16; l++) {
        int idx = tid + l * 256;
        int rr = idx >> 6, cc = idx & 63;
        float tv = T[rr * 68 + cc] * sc;
        T[rr * 68 + cc] = tv;
        Pa[rr * 68 + cc] = tv * 0.125f + (rr == cc ? 1.f : 0.f);
    }
    __syncthreads();

    float* pa = Pa;
    float* pb = Pb;
#pragma unroll
    for (int k = 7; k >= 1; k--) {
        mm64(T, pa, pb, 1.f / (float)k, 1, tid);
        float* t = pa; pa = pb; pb = t;
    }
    for (int sqr = 0; sqr < m; sqr++) {
        mm64(pa, pa, pb, 1.f, 0, tid);
        float* t = pa; pa = pb; pb = t;
    }

    float* om = out + (size_t)mat * 4096;
#pragma unroll
    for (int l = 0; l < 16; l++) {
        int idx = tid + l * 256;
        om[idx] = pa[(idx >> 6) * 68 + (idx & 63)];
    }
}

extern "C" void kernel_launch(void* const* d_in, const int* in_sizes, int n_in,
                              void* d_out, int out_size) {
    const float* X  = (const float*)d_in[0];
    const float* bw = (const float*)d_in[1];
    float* out = (float*)d_out;

    jacobi_log_kernel<<<NMAT, 128>>>(X);
    gram_kernel<<<dim3(8, 8, 4), 256>>>();
    w_kernel<<<NMAT, 256>>>(bw);
    col_kernel<<<NMAT, 256>>>();
    m_kernel<<<dim3(8, 32), 256>>>();
    expm_kernel<<<NMAT, 256>>>(out);
}

// round 5
// speedup vs baseline: 2.2894x; 1.2045x over previous
#include <cuda_runtime.h>
#include <math.h>

#define NMAT 256
#define DD 64
#define NSWEEP 7
#define GZ 8            // gram split-K partitions

__device__ float g_L[NMAT * DD * DD];      // log(X_i)
__device__ float g_S[NMAT * DD * DD];      // log(X_i) + M_i
__device__ float g_gramp[GZ * NMAT * NMAT];
__device__ float g_W[NMAT * NMAT];
__device__ float g_sq[NMAT];
__device__ float g_ss[NMAT];
__device__ float g_row[NMAT];

template <int NW>
__device__ __forceinline__ float blk_reduce(float v, float* red, int tid) {
#pragma unroll
    for (int o = 16; o >= 1; o >>= 1) v += __shfl_xor_sync(0xffffffffu, v, o);
    if ((tid & 31) == 0) red[tid >> 5] = v;
    __syncthreads();
    if (tid == 0) {
        float s = 0.f;
#pragma unroll
        for (int w = 0; w < NW; w++) s += red[w];
        red[0] = s;
    }
    __syncthreads();
    float r = red[0];
    __syncthreads();
    return r;
}

// ============================================================
// Kernel 1: one-sided Jacobi -> log(X); also sq=||L||_F^2, ss=sum(L)
// 128 threads: 4 threads per column-pair, 16 rows (4x float4) each.
// ============================================================
__global__ void __launch_bounds__(128) jacobi_log_kernel(const float* __restrict__ X) {
    __shared__ float G[64 * 68];   // column-major, stride 68
    __shared__ float coef[64];
    __shared__ float red[4];
    const int tid = threadIdx.x;
    const int mat = blockIdx.x;
    const float* Xm = X + (size_t)mat * 4096;

#pragma unroll
    for (int l = 0; l < 32; l++) {
        int idx = tid + l * 128;
        G[(idx >> 6) * 68 + (idx & 63)] = Xm[idx];   // X symmetric
    }
    __syncthreads();

    const int pr = tid >> 2;   // pair 0..31
    const int sub = tid & 3;   // 16 rows (4 float4) per thread

    for (int sweep = 0; sweep < NSWEEP; sweep++) {
        for (int r = 0; r < 63; r++) {
            int a, b;
            if (pr == 0) { a = 63; b = r; }
            else {
                int x = r + pr;       if (x >= 63) x -= 63;
                int y = r + 63 - pr;  if (y >= 63) y -= 63;
                a = x; b = y;
            }
            int p = a < b ? a : b;
            int q = a < b ? b : a;

            float4* gp = (float4*)&G[p * 68 + sub * 16];
            float4* gq = (float4*)&G[q * 68 + sub * 16];
            float4 P[4], Q[4];
#pragma unroll
            for (int i = 0; i < 4; i++) { P[i] = gp[i]; Q[i] = gq[i]; }

            float pp[4], qq[4], pq[4];
#pragma unroll
            for (int i = 0; i < 4; i++) {
                pp[i] = P[i].x*P[i].x + P[i].y*P[i].y + P[i].z*P[i].z + P[i].w*P[i].w;
                qq[i] = Q[i].x*Q[i].x + Q[i].y*Q[i].y + Q[i].z*Q[i].z + Q[i].w*Q[i].w;
                pq[i] = P[i].x*Q[i].x + P[i].y*Q[i].y + P[i].z*Q[i].z + P[i].w*Q[i].w;
            }
            float dpp = (pp[0] + pp[1]) + (pp[2] + pp[3]);
            float dqq = (qq[0] + qq[1]) + (qq[2] + qq[3]);
            float dpq = (pq[0] + pq[1]) + (pq[2] + pq[3]);
#pragma unroll
            for (int o = 1; o < 4; o <<= 1) {
                dpp += __shfl_xor_sync(0xffffffffu, dpp, o);
                dqq += __shfl_xor_sync(0xffffffffu, dqq, o);
                dpq += __shfl_xor_sync(0xffffffffu, dpq, o);
            }

            // skip rotations below fp32 noise (relative threshold)
            if (dpq * dpq > 1e-14f * dpp * dqq) {
                float tau = __fdividef(dqq - dpp, 2.f * dpq);
                float r2 = 1.f + tau * tau;
                float srt = r2 * rsqrtf(r2);                   // sqrt(1+tau^2)
                float t = __fdividef(1.f, fabsf(tau) + srt);
                t = (tau >= 0.f) ? t : -t;
                float c = rsqrtf(1.f + t * t);
                float s = t * c;
#pragma unroll
                for (int i = 0; i < 4; i++) {
                    float4 R, U;
                    R.x = c*P[i].x - s*Q[i].x;  U.x = s*P[i].x + c*Q[i].x;
                    R.y = c*P[i].y - s*Q[i].y;  U.y = s*P[i].y + c*Q[i].y;
                    R.z = c*P[i].z - s*Q[i].z;  U.z = s*P[i].z + c*Q[i].z;
                    R.w = c*P[i].w - s*Q[i].w;  U.w = s*P[i].w + c*Q[i].w;
                    gp[i] = R;
                    gq[i] = U;
                }
            }
            __syncthreads();
        }
    }

    // lambda_j = ||g_j||; log X = sum_j (log l / l^2) g_j g_j^T
    if (tid < 64) {
        float n2 = 0.f;
#pragma unroll 8
        for (int k = 0; k < 64; k++) { float g = G[tid * 68 + k]; n2 += g * g; }
        coef[tid] = 0.5f * logf(n2) / n2;
    }
    __syncthreads();

    const int ty = tid >> 4, tx = tid & 15;        // ty 0..7, tx 0..15
    const int r0 = ty * 8, c0 = tx * 4;
    float acc[8][4];
#pragma unroll
    for (int i = 0; i < 8; i++)
#pragma unroll
        for (int j = 0; j < 4; j++) acc[i][j] = 0.f;

#pragma unroll 4
    for (int j = 0; j < 64; j++) {
        float cf = coef[j];
        float4 b = *(const float4*)&G[j * 68 + c0];
#pragma unroll
        for (int i = 0; i < 8; i++) {
            float av = G[j * 68 + r0 + i] * cf;
            acc[i][0] += av * b.x;
            acc[i][1] += av * b.y;
            acc[i][2] += av * b.z;
            acc[i][3] += av * b.w;
        }
    }

    float s1 = 0.f, s2 = 0.f;
    float* Lm = g_L + (size_t)mat * 4096;
#pragma unroll
    for (int i = 0; i < 8; i++) {
        float4 v;
        v.x = acc[i][0]; v.y = acc[i][1]; v.z = acc[i][2]; v.w = acc[i][3];
        *(float4*)&Lm[(r0 + i) * 64 + c0] = v;
        s1 += v.x + v.y + v.z + v.w;
        s2 += v.x*v.x + v.y*v.y + v.z*v.z + v.w*v.w;
    }
    float ts1 = blk_reduce<4>(s1, red, tid);
    float ts2 = blk_reduce<4>(s2, red, tid);
    if (tid == 0) { g_ss[mat] = ts1; g_sq[mat] = ts2; }
}

// ============================================================
// Kernel 2: split-K Gram, 64x64 tile, 4x4 per thread, k-major smem
// ============================================================
__global__ void __launch_bounds__(256) gram_kernel() {
    __shared__ float At[64 * 68];   // At[k][i] (k-major), stride 68
    __shared__ float Bt[64 * 68];   // Bt[k][j]
    const int tid = threadIdx.x;
    const int i0 = blockIdx.x * 64, j0 = blockIdx.y * 64, z = blockIdx.z;
    const int kb = z * (4096 / GZ);
    const int ty = tid >> 4, tx = tid & 15;
    float acc[4][4];
#pragma unroll
    for (int i = 0; i < 4; i++)
#pragma unroll
        for (int j = 0; j < 4; j++) acc[i][j] = 0.f;

    for (int kt = 0; kt < (4096 / GZ) / 64; kt++) {
        int kbase = kb + kt * 64;
#pragma unroll
        for (int l = 0; l < 16; l++) {
            int idx = tid + l * 256;
            int rr = idx >> 6, cc = idx & 63;   // rr = matrix row, cc = k
            At[cc * 68 + rr] = g_L[(size_t)(i0 + rr) * 4096 + kbase + cc];
            Bt[cc * 68 + rr] = g_L[(size_t)(j0 + rr) * 4096 + kbase + cc];
        }
        __syncthreads();
#pragma unroll 8
        for (int kk = 0; kk < 64; kk++) {
            float4 a = *(const float4*)&At[kk * 68 + 4 * ty];
            float4 b = *(const float4*)&Bt[kk * 68 + 4 * tx];
            acc[0][0] += a.x*b.x; acc[0][1] += a.x*b.y; acc[0][2] += a.x*b.z; acc[0][3] += a.x*b.w;
            acc[1][0] += a.y*b.x; acc[1][1] += a.y*b.y; acc[1][2] += a.y*b.z; acc[1][3] += a.y*b.w;
            acc[2][0] += a.z*b.x; acc[2][1] += a.z*b.y; acc[2][2] += a.z*b.z; acc[2][3] += a.z*b.w;
            acc[3][0] += a.w*b.x; acc[3][1] += a.w*b.y; acc[3][2] += a.w*b.z; acc[3][3] += a.w*b.w;
        }
        __syncthreads();
    }
    float* gp = g_gramp + (size_t)z * NMAT * NMAT;
#pragma unroll
    for (int i = 0; i < 4; i++) {
        float4 v;
        v.x = acc[i][0]; v.y = acc[i][1]; v.z = acc[i][2]; v.w = acc[i][3];
        *(float4*)&gp[(size_t)(i0 + 4*ty + i) * NMAT + j0 + 4*tx] = v;
    }
}

// ============================================================
// Kernel 3: W + row sums
// ============================================================
__global__ void __launch_bounds__(256) w_kernel(const float* __restrict__ bwp) {
    __shared__ float red[8];
    const int i = blockIdx.x, j = threadIdx.x;
    const float bw = bwp[0];
    const float inv = 0.5f / (bw * bw);
    float gram = 0.f;
#pragma unroll
    for (int z = 0; z < GZ; z++)
        gram += g_gramp[(size_t)z * NMAT * NMAT + i * NMAT + j];
    float pds = g_sq[i] + g_sq[j] - 2.f * gram
              + 2.0e-7f * (g_ss[j] - g_ss[i]) + 4.096e-11f;
    float w = expf(-pds * inv);
    g_W[i * NMAT + j] = w;
    float rs = blk_reduce<8>(w, red, j);
    if (j == 0) g_row[i] = rs;
}

// ============================================================
// Kernel 4: C[k] = sum_j W[j,k] L_j ; S = L + (C - col*L)/row
// col sums fused (streams full j range per k)
// ============================================================
__global__ void __launch_bounds__(256) m_kernel() {
    __shared__ float Ws[32 * 33];
    __shared__ float Ls[32 * 128];
    const int tid = threadIdx.x;
    const int k0 = blockIdx.x * 32;
    const int e0 = blockIdx.y * 128;
    const int kk = tid >> 3;
    const int ee = (tid & 7) * 16;
    float4 acc[4];
#pragma unroll
    for (int i = 0; i < 4; i++) acc[i] = make_float4(0.f, 0.f, 0.f, 0.f);
    float wcol = 0.f;

    for (int jt = 0; jt < 8; jt++) {
        int j0 = jt * 32;
#pragma unroll
        for (int l = 0; l < 4; l++) {
            int idx = tid + l * 256;
            int j = idx >> 5, k = idx & 31;
            Ws[j * 33 + k] = g_W[(size_t)(j0 + j) * NMAT + k0 + k];
        }
#pragma unroll
        for (int l = 0; l < 4; l++) {
            int idx = tid + l * 256;
            int j = idx >> 5, c4 = idx & 31;
            ((float4*)Ls)[j * 32 + c4] =
                ((const float4*)(g_L + (size_t)(j0 + j) * 4096 + e0))[c4];
        }
        __syncthreads();
#pragma unroll 8
        for (int j = 0; j < 32; j++) {
            float w = Ws[j * 33 + kk];
            wcol += w;
            const float4* lr = (const float4*)(Ls + j * 128 + ee);
            float4 l0 = lr[0], l1 = lr[1], l2 = lr[2], l3 = lr[3];
            acc[0].x += w*l0.x; acc[0].y += w*l0.y; acc[0].z += w*l0.z; acc[0].w += w*l0.w;
            acc[1].x += w*l1.x; acc[1].y += w*l1.y; acc[1].z += w*l1.z; acc[1].w += w*l1.w;
            acc[2].x += w*l2.x; acc[2].y += w*l2.y; acc[2].z += w*l2.z; acc[2].w += w*l2.w;
            acc[3].x += w*l3.x; acc[3].y += w*l3.y; acc[3].z += w*l3.z; acc[3].w += w*l3.w;
        }
        __syncthreads();
    }

    const int k = k0 + kk;
    const float col = wcol;
    const float rinv = __fdividef(1.f, g_row[k]);
    const float4* Lk = (const float4*)(g_L + (size_t)k * 4096 + e0 + ee);
    float4* Sk = (float4*)(g_S + (size_t)k * 4096 + e0 + ee);
#pragma unroll
    for (int i = 0; i < 4; i++) {
        float4 lv = Lk[i];
        float4 o;
        o.x = lv.x + (acc[i].x - col * lv.x) * rinv;
        o.y = lv.y + (acc[i].y - col * lv.y) * rinv;
        o.z = lv.z + (acc[i].z - col * lv.z) * rinv;
        o.w = lv.w + (acc[i].w - col * lv.w) * rinv;
        Sk[i] = o;
    }
}

// ============================================================
// Kernel 5: exp(S) via scaling & squaring (deg-7 Taylor, ||T||<=0.5)
// ============================================================
__device__ __forceinline__ void mm64(const float* A, const float* B, float* C,
                                     float scale, int addI, int tid) {
    const int ty = tid >> 4, tx = tid & 15;
    const int r0 = ty * 4, c0 = tx * 4;
    float acc[4][4];
#pragma unroll
    for (int i = 0; i < 4; i++)
#pragma unroll
        for (int j = 0; j < 4; j++) acc[i][j] = 0.f;
#pragma unroll 4
    for (int k4 = 0; k4 < 64; k4 += 4) {
        float4 a0 = *(const float4*)&A[(r0 + 0) * 68 + k4];
        float4 a1 = *(const float4*)&A[(r0 + 1) * 68 + k4];
        float4 a2 = *(const float4*)&A[(r0 + 2) * 68 + k4];
        float4 a3 = *(const float4*)&A[(r0 + 3) * 68 + k4];
        float4 b0 = *(const float4*)&B[(k4 + 0) * 68 + c0];
        float4 b1 = *(const float4*)&B[(k4 + 1) * 68 + c0];
        float4 b2 = *(const float4*)&B[(k4 + 2) * 68 + c0];
        float4 b3 = *(const float4*)&B[(k4 + 3) * 68 + c0];
#define MMSTEP(ai, bk) \
        acc[0][0] += a0.ai*bk.x; acc[0][1] += a0.ai*bk.y; acc[0][2] += a0.ai*bk.z; acc[0][3] += a0.ai*bk.w; \
        acc[1][0] += a1.ai*bk.x; acc[1][1] += a1.ai*bk.y; acc[1][2] += a1.ai*bk.z; acc[1][3] += a1.ai*bk.w; \
        acc[2][0] += a2.ai*bk.x; acc[2][1] += a2.ai*bk.y; acc[2][2] += a2.ai*bk.z; acc[2][3] += a2.ai*bk.w; \
        acc[3][0] += a3.ai*bk.x; acc[3][1] += a3.ai*bk.y; acc[3][2] += a3.ai*bk.z; acc[3][3] += a3.ai*bk.w;
        MMSTEP(x, b0)
        MMSTEP(y, b1)
        MMSTEP(z, b2)
        MMSTEP(w, b3)
#undef MMSTEP
    }
#pragma unroll
    for (int i = 0; i < 4; i++)
#pragma unroll
        for (int j = 0; j < 4; j++) {
            float v = acc[i][j] * scale;
            if (addI && (r0 + i) == (c0 + j)) v += 1.f;
            C[(r0 + i) * 68 + c0 + j] = v;
        }
    __syncthreads();
}

__global__ void __launch_bounds__(256) expm_kernel(float* __restrict__ out) {
    __shared__ float T[64 * 68];
    __shared__ float Pa[64 * 68];
    __shared__ float Pb[64 * 68];
    __shared__ float red[8];
    const int tid = threadIdx.x;
    const int mat = blockIdx.x;
    const float* Sm = g_S + (size_t)mat * 4096;

    float fr = 0.f;
#pragma unroll
    for (int l = 0; l < 16; l++) {
        int idx = tid + l * 256;
        float v = Sm[idx];
        T[(idx >> 6) * 68 + (idx & 63)] = v;
        fr += v * v;
    }
    float fro2 = blk_reduce<8>(fr, red, tid);
    float fro = sqrtf(fro2);

    int m = 0;
    float sc = 1.f;
    while (fro * sc > 0.5f && m < 30) { sc *= 0.5f; m++; }

    // scale T; init A = I + T/7 (deg-7 Horner innermost step)
#pragma unroll
    for (int l = 0; l < 16; l++) {
        int idx = tid + l * 256;
        int rr = idx >> 6, cc = idx & 63;
        float tv = T[rr * 68 + cc] * sc;
        T[rr * 68 + cc] = tv;
        Pa[rr * 68 + cc] = tv * (1.f / 7.f) + (rr == cc ? 1.f : 0.f);
    }
    __syncthreads();

    float* pa = Pa;
    float* pb = Pb;
#pragma unroll
    for (int k = 6; k >= 1; k--) {
        mm64(T, pa, pb, 1.f / (float)k, 1, tid);
        float* t = pa; pa = pb; pb = t;
    }
    for (int sqr = 0; sqr < m; sqr++) {
        mm64(pa, pa, pb, 1.f, 0, tid);
        float* t = pa; pa = pb; pb = t;
    }

    float* om = out + (size_t)mat * 4096;
#pragma unroll
    for (int l = 0; l < 16; l++) {
        int idx = tid + l * 256;
        om[idx] = pa[(idx >> 6) * 68 + (idx & 63)];
    }
}

extern "C" void kernel_launch(void* const* d_in, const int* in_sizes, int n_in,
                              void* d_out, int out_size) {
    const float* X  = (const float*)d_in[0];
    const float* bw = (const float*)d_in[1];
    float* out = (float*)d_out;

    jacobi_log_kernel<<<NMAT, 128>>>(X);
    gram_kernel<<<dim3(4, 4, GZ), 256>>>();
    w_kernel<<<NMAT, 256>>>(bw);
    m_kernel<<<dim3(8, 32), 256>>>();
    expm_kernel<<<NMAT, 256>>>(out);
}